// round 9
// baseline (speedup 1.0000x reference)
#include <cuda_runtime.h>
#include <cuda_fp16.h>
#include <math.h>
#include <stdint.h>

#define DIMV   100
#define TSTEPS 100
#define NT     256
#define MT     64          // rows per CTA -> 64 CTAs
#define AST    108         // A row stride in u32 (conflict-free)
#define SST    102         // S row stride in floats (even -> float2)
#define NPAD_H 200
#define NPAD_O 104
#define BUFB   19200       // bytes per B stage buffer (200 rows * 48B * 2 halves)
#define TOTCH  5900        // 59 chunks/step * 100 steps

// weight pool: per layer, per k16-step: [npad][8] u32 hi then [npad][8] u32 lo
#define OFF_L0 0
#define OFF_L1 22400
#define OFF_L2 64000
#define OFF_L3 105600
#define OFF_LO 147200
__device__ __align__(16) uint32_t g_Bpk[168832];

// ---------- helpers ----------
__device__ __forceinline__ void hsplit2(float f0, float f1, uint32_t& hi, uint32_t& lo) {
    __half h0 = __float2half_rn(f0), h1 = __float2half_rn(f1);
    __half l0 = __float2half_rn(f0 - __half2float(h0));
    __half l1 = __float2half_rn(f1 - __half2float(h1));
    hi = ((uint32_t)__half_as_ushort(h1) << 16) | __half_as_ushort(h0);
    lo = ((uint32_t)__half_as_ushort(l1) << 16) | __half_as_ushort(l0);
}
__device__ __forceinline__ void mma16816(float* c, const uint32_t* a, const uint32_t* b) {
    asm volatile("mma.sync.aligned.m16n8k16.row.col.f32.f16.f16.f32 "
        "{%0,%1,%2,%3}, {%4,%5,%6,%7}, {%8,%9}, {%0,%1,%2,%3};"
        : "+f"(c[0]), "+f"(c[1]), "+f"(c[2]), "+f"(c[3])
        : "r"(a[0]), "r"(a[1]), "r"(a[2]), "r"(a[3]), "r"(b[0]), "r"(b[1]));
}
__device__ __forceinline__ void cpa16(void* d, const void* s) {
    unsigned a = (unsigned)__cvta_generic_to_shared(d);
    asm volatile("cp.async.cg.shared.global [%0], [%1], 16;" :: "r"(a), "l"(s));
}
__device__ __forceinline__ void cpcommit() { asm volatile("cp.async.commit_group;"); }
template<int N> __device__ __forceinline__ void cpwait() {
    asm volatile("cp.async.wait_group %0;" :: "n"(N));
}

// ---------- weight pack: fp16 split + transpose to [ks][n][kp] ----------
__global__ void pack_b(const float* __restrict__ W, int Kr, int Nr, int npad,
                       int ksteps, int off) {
    int idx = blockIdx.x * blockDim.x + threadIdx.x;
    if (idx >= ksteps * npad * 8) return;
    int ks = idx / (npad * 8), r = idx - ks * npad * 8, n = r >> 3, kp = r & 7;
    int k0 = ks * 16 + kp * 2, k1 = k0 + 1;
    float v0 = (k0 < Kr && n < Nr) ? W[(size_t)k0 * Nr + n] : 0.0f;
    float v1 = (k1 < Kr && n < Nr) ? W[(size_t)k1 * Nr + n] : 0.0f;
    uint32_t hi, lo; hsplit2(v0, v1, hi, lo);
    int b = off + ks * npad * 16;
    g_Bpk[b + n * 8 + kp] = hi;
    g_Bpk[b + npad * 8 + n * 8 + kp] = lo;
}

// ---------- chunk staging: global pool -> smem [n][12] u32 (stride 48B) ----------
__device__ __forceinline__ void stage(int cs, char* dst, int tid) {
    int base, ki, npad;
    if      (cs < 7)  { base = OFF_L0; ki = cs;      npad = NPAD_H; }
    else if (cs < 20) { base = OFF_L1; ki = cs - 7;  npad = NPAD_H; }
    else if (cs < 33) { base = OFF_L2; ki = cs - 20; npad = NPAD_H; }
    else if (cs < 46) { base = OFF_L3; ki = cs - 33; npad = NPAD_H; }
    else              { base = OFF_LO; ki = cs - 46; npad = NPAD_O; }
    const char* src = (const char*)(g_Bpk + base + (size_t)ki * npad * 16);
    int nf = npad * 4;
    for (int f = tid; f < nf; f += NT)
        cpa16(dst + (f >> 1) * 48 + (f & 1) * 16, src + (f >> 1) * 32 + (f & 1) * 16);
    cpcommit();
}
__device__ __forceinline__ void chunk_sync(int gc) {
    if (gc + 1 < TOTCH) cpwait<1>(); else cpwait<0>();
    __syncthreads();
}

// ---------- hidden-layer GEMM + epilogue (warp grid 2m x 4n) ----------
__device__ __forceinline__ void gemm_hidden(
    int KS, uint32_t* Ahi, uint32_t* Alo, char* bbuf, int& gc,
    const float* bias, int wm, int wn, int g, int tq, int tid)
{
    float acc[2][7][4];
    #pragma unroll
    for (int a = 0; a < 2; ++a)
        #pragma unroll
        for (int b = 0; b < 7; ++b)
            #pragma unroll
            for (int c = 0; c < 4; ++c) acc[a][b][c] = 0.0f;

    for (int ks = 0; ks < KS; ++ks) {
        chunk_sync(gc);
        if (gc + 2 < TOTCH) stage((gc + 2) % 59, bbuf + ((gc + 2) % 3) * BUFB, tid);
        const char* bc = bbuf + (gc % 3) * BUFB;

        uint32_t Ah[2][4], Al[2][4];
        #pragma unroll
        for (int mf = 0; mf < 2; ++mf)
            #pragma unroll
            for (int r = 0; r < 4; ++r) {
                int row = wm * 32 + mf * 16 + g + (r & 1) * 8;
                int kp  = ks * 8 + tq + (r >> 1) * 4;
                Ah[mf][r] = Ahi[row * AST + kp];
                Al[mf][r] = Alo[row * AST + kp];
            }
        #pragma unroll
        for (int nf = 0; nf < 7; ++nf) {
            int base = wn * 56 + nf * 8;
            if (base >= 200) break;
            const char* bp = bc + (base + g) * 48 + tq * 4;
            uint32_t Bh[2], Bl[2];
            Bh[0] = *(const uint32_t*)bp;
            Bh[1] = *(const uint32_t*)(bp + 16);
            Bl[0] = *(const uint32_t*)(bp + NPAD_H * 48);
            Bl[1] = *(const uint32_t*)(bp + NPAD_H * 48 + 16);
            #pragma unroll
            for (int mf = 0; mf < 2; ++mf) {
                mma16816(acc[mf][nf], Ah[mf], Bh);
                mma16816(acc[mf][nf], Ah[mf], Bl);
                mma16816(acc[mf][nf], Al[mf], Bh);
            }
        }
        ++gc;
    }
    __syncthreads();   // all reads of A done before overwriting

    #pragma unroll
    for (int mf = 0; mf < 2; ++mf)
        #pragma unroll
        for (int nf = 0; nf < 7; ++nf) {
            int base = wn * 56 + nf * 8;
            if (base >= 200) break;
            int n0 = base + tq * 2;
            float bv0 = bias[n0], bv1 = bias[n0 + 1];
            int kp = (base >> 1) + tq;
            int row = wm * 32 + mf * 16 + g;
            uint32_t hi, lo;
            hsplit2(fmaxf(acc[mf][nf][0] + bv0, 0.0f),
                    fmaxf(acc[mf][nf][1] + bv1, 0.0f), hi, lo);
            Ahi[row * AST + kp] = hi; Alo[row * AST + kp] = lo;
            hsplit2(fmaxf(acc[mf][nf][2] + bv0, 0.0f),
                    fmaxf(acc[mf][nf][3] + bv1, 0.0f), hi, lo);
            Ahi[(row + 8) * AST + kp] = hi; Alo[(row + 8) * AST + kp] = lo;
        }
    // next layer's first chunk_sync orders these writes before reads
}

// ---------- main persistent kernel ----------
#define SMEM_BYTES 143104

__global__ void __launch_bounds__(NT, 1)
control_solver_hmma(
    const float* __restrict__ S0, const float* __restrict__ tg,
    const float* __restrict__ dW,
    const float* __restrict__ b0, const float* __restrict__ b1,
    const float* __restrict__ b2, const float* __restrict__ b3,
    const float* __restrict__ bout, float* __restrict__ out)
{
    extern __shared__ __align__(16) char smc[];
    uint32_t* Ahi = (uint32_t*)smc;                  // 64*108*4 = 27648 B
    uint32_t* Alo = Ahi + MT * AST;                  // 27648 B
    char* bbuf    = (char*)(Alo + MT * AST);         // 3*19200 = 57600 B
    float* S      = (float*)(bbuf + 3 * BUFB);       // 64*102*4 = 26112 B
    float* sbv    = S + MT * SST;                    // 900 biases
    float* tgs    = sbv + 900;                       // 101 timegrid

    const int tid = threadIdx.x, warp = tid >> 5, lane = tid & 31;
    const int g = lane >> 2, tq = lane & 3;
    const int wm = warp >> 2, wn = warp & 3;          // hidden grid 2x4
    const int owm = warp >> 1, own = warp & 1;        // out grid 4x2
    const int gm0 = blockIdx.x * MT;

    stage(0, bbuf, tid);
    stage(1, bbuf + BUFB, tid);

    for (int i = tid; i < 200; i += NT) {
        sbv[i] = b0[i]; sbv[200 + i] = b1[i]; sbv[400 + i] = b2[i]; sbv[600 + i] = b3[i];
        if (i < 100) sbv[800 + i] = bout[i];
    }
    for (int i = tid; i <= TSTEPS; i += NT) tgs[i] = tg[i];
    for (int i = tid; i < MT * DIMV; i += NT) {
        int m = i / DIMV, c = i - m * DIMV;
        S[m * SST + c] = S0[(size_t)(gm0 + m) * DIMV + c];
    }
    for (int i = tid; i < MT * 8; i += NT) {         // zero A kpairs 100..107
        int row = i >> 3, kp = 100 + (i & 7);
        Ahi[row * AST + kp] = 0; Alo[row * AST + kp] = 0;
    }
    __syncthreads();
    const float h = tgs[1] - tgs[0];
    const float sqh = sqrtf(h);

    int gc = 0;
    for (int t = 0; t < TSTEPS; ++t) {
        // build A0 = [t | S | 0pad] as fp16 hi/lo, kpairs 0..55
        {
            int row = tid >> 2, q = tid & 3;
            float tval = tgs[t];
            #pragma unroll
            for (int jj = 0; jj < 14; ++jj) {
                int j = q * 14 + jj, k0 = 2 * j;
                float f0 = (k0 == 0) ? tval : ((k0 <= 100) ? S[row * SST + k0 - 1] : 0.0f);
                float f1 = (k0 + 1 <= 100) ? S[row * SST + k0] : 0.0f;
                uint32_t hi, lo; hsplit2(f0, f1, hi, lo);
                Ahi[row * AST + j] = hi; Alo[row * AST + j] = lo;
            }
        }
        gemm_hidden(7,  Ahi, Alo, bbuf, gc, sbv,       wm, wn, g, tq, tid);
        gemm_hidden(13, Ahi, Alo, bbuf, gc, sbv + 200, wm, wn, g, tq, tid);
        gemm_hidden(13, Ahi, Alo, bbuf, gc, sbv + 400, wm, wn, g, tq, tid);
        gemm_hidden(13, Ahi, Alo, bbuf, gc, sbv + 600, wm, wn, g, tq, tid);

        // ---- output layer (grid 4m x 2n, npad 104) ----
        float acc[7][4];
        #pragma unroll
        for (int b = 0; b < 7; ++b)
            #pragma unroll
            for (int c = 0; c < 4; ++c) acc[b][c] = 0.0f;

        for (int ks = 0; ks < 13; ++ks) {
            chunk_sync(gc);
            if (gc + 2 < TOTCH) stage((gc + 2) % 59, bbuf + ((gc + 2) % 3) * BUFB, tid);
            const char* bc = bbuf + (gc % 3) * BUFB;
            uint32_t Ah[4], Al[4];
            #pragma unroll
            for (int r = 0; r < 4; ++r) {
                int row = owm * 16 + g + (r & 1) * 8;
                int kp  = ks * 8 + tq + (r >> 1) * 4;
                Ah[r] = Ahi[row * AST + kp];
                Al[r] = Alo[row * AST + kp];
            }
            #pragma unroll
            for (int nf = 0; nf < 7; ++nf) {
                int base = own * 56 + nf * 8;
                if (base >= 100) break;
                const char* bp = bc + (base + g) * 48 + tq * 4;
                uint32_t Bh[2], Bl[2];
                Bh[0] = *(const uint32_t*)bp;
                Bh[1] = *(const uint32_t*)(bp + 16);
                Bl[0] = *(const uint32_t*)(bp + NPAD_O * 48);
                Bl[1] = *(const uint32_t*)(bp + NPAD_O * 48 + 16);
                mma16816(acc[nf], Ah, Bh);
                mma16816(acc[nf], Ah, Bl);
                mma16816(acc[nf], Al, Bh);
            }
            ++gc;
        }
        __syncthreads();

        // ---- SDE epilogue: u = D + bout; err->out (rmw); S update ----
        #pragma unroll
        for (int nf = 0; nf < 7; ++nf) {
            int base = own * 56 + nf * 8;
            if (base >= 100) break;
            int n0 = base + tq * 2;
            if (n0 < 100) {
                float bv0 = sbv[800 + n0], bv1 = sbv[800 + n0 + 1];
                #pragma unroll
                for (int hf = 0; hf < 2; ++hf) {
                    int m = owm * 16 + g + 8 * hf;
                    float u0 = acc[nf][2 * hf]     + bv0;
                    float u1 = acc[nf][2 * hf + 1] + bv1;
                    float2 dw = *(const float2*)(dW + (size_t)(gm0 + m) * 10100
                                                    + (size_t)t * DIMV + n0);
                    float s0 = S[m * SST + n0]     + u0 * (h + sqh * dw.x);
                    float s1 = S[m * SST + n0 + 1] + u1 * (h + sqh * dw.y);
                    float2* op = (float2*)(out + (size_t)(gm0 + m) * DIMV + n0);
                    float2 prev = (t == 0) ? make_float2(0.0f, 0.0f) : *op;
                    float o0 = prev.x + u0 * u0 * h;
                    float o1 = prev.y + u1 * u1 * h;
                    if (t == TSTEPS - 1) { o0 += s0 * s0; o1 += s1 * s1; }
                    else { S[m * SST + n0] = s0; S[m * SST + n0 + 1] = s1; }
                    *op = make_float2(o0, o1);
                }
            }
        }
        __syncthreads();   // S stable before next build_A0
    }
    cpwait<0>();
}

extern "C" void kernel_launch(void* const* d_in, const int* in_sizes, int n_in,
                              void* d_out, int out_size) {
    const float* S0   = (const float*)d_in[0];
    const float* tg   = (const float*)d_in[1];
    const float* dW   = (const float*)d_in[2];
    const float* W0   = (const float*)d_in[3];
    const float* b0   = (const float*)d_in[4];
    const float* W1   = (const float*)d_in[5];
    const float* b1   = (const float*)d_in[6];
    const float* W2   = (const float*)d_in[7];
    const float* b2   = (const float*)d_in[8];
    const float* W3   = (const float*)d_in[9];
    const float* b3   = (const float*)d_in[10];
    const float* Wout = (const float*)d_in[11];
    const float* bout = (const float*)d_in[12];
    float* out = (float*)d_out;

    pack_b<<<(7  * 200 * 8 + 255) / 256, 256>>>(W0,   101, 200, 200, 7,  OFF_L0);
    pack_b<<<(13 * 200 * 8 + 255) / 256, 256>>>(W1,   200, 200, 200, 13, OFF_L1);
    pack_b<<<(13 * 200 * 8 + 255) / 256, 256>>>(W2,   200, 200, 200, 13, OFF_L2);
    pack_b<<<(13 * 200 * 8 + 255) / 256, 256>>>(W3,   200, 200, 200, 13, OFF_L3);
    pack_b<<<(13 * 104 * 8 + 255) / 256, 256>>>(Wout, 200, 100, 104, 13, OFF_LO);

    cudaFuncSetAttribute(control_solver_hmma,
                         cudaFuncAttributeMaxDynamicSharedMemorySize, SMEM_BYTES);
    control_solver_hmma<<<4096 / MT, NT, SMEM_BYTES>>>(
        S0, tg, dW, b0, b1, b2, b3, bout, out);
}

// round 10
// speedup vs baseline: 1.4390x; 1.4390x over previous
#include <cuda_runtime.h>
#include <cuda_fp16.h>
#include <math.h>
#include <stdint.h>

#define DIMV   100
#define TSTEPS 100
#define NT     256
#define MT     32          // rows per CTA -> 128 CTAs
#define AST    108         // A row stride in u32 (conflict-free)
#define SST    102         // S row stride in floats
#define KSB    19200       // smem bytes per kstep sub-buffer (2*200 rows * 48B)
#define BUFB   38400       // bytes per chunk buffer (2 ksteps)
#define NCHSTEP 32         // chunks per step: L0:4, L1..L3:7 each, out:7
#define TOTCH  (NCHSTEP * TSTEPS)

// weight pool: per layer, per k16-step: [npad][8] u32 hi then [npad][8] u32 lo
#define OFF_L0 0
#define OFF_L1 22400
#define OFF_L2 64000
#define OFF_L3 105600
#define OFF_LO 147200
__device__ __align__(16) uint32_t g_Bpk[168832];

// ---------- helpers ----------
__device__ __forceinline__ void hsplit2(float f0, float f1, uint32_t& hi, uint32_t& lo) {
    __half h0 = __float2half_rn(f0), h1 = __float2half_rn(f1);
    __half l0 = __float2half_rn(f0 - __half2float(h0));
    __half l1 = __float2half_rn(f1 - __half2float(h1));
    hi = ((uint32_t)__half_as_ushort(h1) << 16) | __half_as_ushort(h0);
    lo = ((uint32_t)__half_as_ushort(l1) << 16) | __half_as_ushort(l0);
}
__device__ __forceinline__ void mma16816(float* c, const uint32_t* a, const uint32_t* b) {
    asm volatile("mma.sync.aligned.m16n8k16.row.col.f32.f16.f16.f32 "
        "{%0,%1,%2,%3}, {%4,%5,%6,%7}, {%8,%9}, {%0,%1,%2,%3};"
        : "+f"(c[0]), "+f"(c[1]), "+f"(c[2]), "+f"(c[3])
        : "r"(a[0]), "r"(a[1]), "r"(a[2]), "r"(a[3]), "r"(b[0]), "r"(b[1]));
}
__device__ __forceinline__ void cpa16(void* d, const void* s) {
    unsigned a = (unsigned)__cvta_generic_to_shared(d);
    asm volatile("cp.async.cg.shared.global [%0], [%1], 16;" :: "r"(a), "l"(s));
}
__device__ __forceinline__ void cpcommit() { asm volatile("cp.async.commit_group;"); }
template<int N> __device__ __forceinline__ void cpwait() {
    asm volatile("cp.async.wait_group %0;" :: "n"(N));
}

// ---------- weight pack: fp16 split + transpose to [ks][n][kp] ----------
__global__ void pack_b(const float* __restrict__ W, int Kr, int Nr, int npad,
                       int ksteps, int off) {
    int idx = blockIdx.x * blockDim.x + threadIdx.x;
    if (idx >= ksteps * npad * 8) return;
    int ks = idx / (npad * 8), r = idx - ks * npad * 8, n = r >> 3, kp = r & 7;
    int k0 = ks * 16 + kp * 2, k1 = k0 + 1;
    float v0 = (k0 < Kr && n < Nr) ? W[(size_t)k0 * Nr + n] : 0.0f;
    float v1 = (k1 < Kr && n < Nr) ? W[(size_t)k1 * Nr + n] : 0.0f;
    uint32_t hi, lo; hsplit2(v0, v1, hi, lo);
    int b = off + ks * npad * 16;
    g_Bpk[b + n * 8 + kp] = hi;
    g_Bpk[b + npad * 8 + n * 8 + kp] = lo;
}

// ---------- chunk metadata (cs in [0,32)) ----------
__device__ __forceinline__ void chunk_meta(int cs, int& off, int& ks0, int& nk, int& npad) {
    if (cs < 4) { off = OFF_L0; ks0 = 2 * cs; nk = (cs == 3) ? 1 : 2; npad = 200; }
    else {
        int r = cs - 4, L = r / 7, ci = r - 7 * L;
        ks0 = 2 * ci; nk = (ci == 6) ? 1 : 2;
        npad = (L == 3) ? 104 : 200;
        off = (L == 0) ? OFF_L1 : (L == 1) ? OFF_L2 : (L == 2) ? OFF_L3 : OFF_LO;
    }
}

// ---------- staging: pool kstep blocks -> smem [2n rows][48B stride] ----------
__device__ __forceinline__ void stage(int cs, char* dst, int tid) {
    int off, ks0, nk, npad;
    chunk_meta(cs, off, ks0, nk, npad);
    for (int ki = 0; ki < nk; ++ki) {
        const char* src = (const char*)(g_Bpk + off + (size_t)(ks0 + ki) * npad * 16);
        char* d = dst + ki * KSB;
        int nf = npad * 4;
        for (int f = tid; f < nf; f += NT)
            cpa16(d + (f >> 1) * 48 + (f & 1) * 16, src + (f >> 1) * 32 + (f & 1) * 16);
    }
    cpcommit();
}
__device__ __forceinline__ void chunk_sync(int gc) {
    if (gc + 1 < TOTCH) cpwait<1>(); else cpwait<0>();
    __syncthreads();
}

// ---------- hidden-layer GEMM + epilogue (warp grid 2m x 4n, 16 rows/warp) ----------
__device__ __forceinline__ void gemm_hidden(
    int KS, int NCH, uint32_t* Ahi, uint32_t* Alo, char* bbuf, int& gc,
    const float* bias, int wm, int wn, int g, int tq, int tid)
{
    float acc[7][4];
    #pragma unroll
    for (int b = 0; b < 7; ++b)
        #pragma unroll
        for (int c = 0; c < 4; ++c) acc[b][c] = 0.0f;

    for (int ch = 0; ch < NCH; ++ch) {
        int nk = KS - 2 * ch; if (nk > 2) nk = 2;
        chunk_sync(gc);
        if (gc + 2 < TOTCH) stage((gc + 2) % NCHSTEP, bbuf + ((gc + 2) % 3) * BUFB, tid);
        const char* bc = bbuf + (gc % 3) * BUFB;

        for (int ki = 0; ki < nk; ++ki) {
            int ks = 2 * ch + ki;
            uint32_t Ah[4], Al[4];
            #pragma unroll
            for (int r = 0; r < 4; ++r) {
                int row = wm * 16 + g + (r & 1) * 8;
                int kp  = ks * 8 + tq + (r >> 1) * 4;
                Ah[r] = Ahi[row * AST + kp];
                Al[r] = Alo[row * AST + kp];
            }
            const char* bck = bc + ki * KSB;
            #pragma unroll
            for (int nf = 0; nf < 7; ++nf) {
                int base = wn * 56 + nf * 8;
                if (base >= 200) break;
                const char* bp = bck + (base + g) * 48 + tq * 4;
                uint32_t Bh[2], Bl[2];
                Bh[0] = *(const uint32_t*)bp;
                Bh[1] = *(const uint32_t*)(bp + 16);
                Bl[0] = *(const uint32_t*)(bp + 200 * 48);
                Bl[1] = *(const uint32_t*)(bp + 200 * 48 + 16);
                mma16816(acc[nf], Ah, Bh);
                mma16816(acc[nf], Ah, Bl);
                mma16816(acc[nf], Al, Bh);
            }
        }
        ++gc;
    }
    __syncthreads();   // all reads of A done before overwriting

    #pragma unroll
    for (int nf = 0; nf < 7; ++nf) {
        int base = wn * 56 + nf * 8;
        if (base >= 200) break;
        int n0 = base + tq * 2;
        float bv0 = bias[n0], bv1 = bias[n0 + 1];
        int kp = (base >> 1) + tq;
        int row = wm * 16 + g;
        uint32_t hi, lo;
        hsplit2(fmaxf(acc[nf][0] + bv0, 0.0f), fmaxf(acc[nf][1] + bv1, 0.0f), hi, lo);
        Ahi[row * AST + kp] = hi; Alo[row * AST + kp] = lo;
        hsplit2(fmaxf(acc[nf][2] + bv0, 0.0f), fmaxf(acc[nf][3] + bv1, 0.0f), hi, lo);
        Ahi[(row + 8) * AST + kp] = hi; Alo[(row + 8) * AST + kp] = lo;
    }
    // next layer's first chunk_sync orders these writes before reads
}

// ---------- main persistent kernel ----------
#define SMEM_BYTES 160000

__global__ void __launch_bounds__(NT, 1)
control_solver_hmma(
    const float* __restrict__ S0, const float* __restrict__ tg,
    const float* __restrict__ dW,
    const float* __restrict__ b0, const float* __restrict__ b1,
    const float* __restrict__ b2, const float* __restrict__ b3,
    const float* __restrict__ bout, float* __restrict__ out)
{
    extern __shared__ __align__(16) char smc[];
    uint32_t* Ahi = (uint32_t*)smc;                  // 32*108*4 = 13824 B
    uint32_t* Alo = Ahi + MT * AST;                  // 13824 B
    char* bbuf    = (char*)(Alo + MT * AST);         // 3*38400 = 115200 B
    float* S      = (float*)(bbuf + 3 * BUFB);       // 32*102*4 = 13056 B
    float* sbv    = S + MT * SST;                    // 900 biases
    float* tgs    = sbv + 900;                       // 101 timegrid

    const int tid = threadIdx.x, warp = tid >> 5, lane = tid & 31;
    const int g = lane >> 2, tq = lane & 3;
    const int wm = warp >> 2, wn = warp & 3;          // 2m x 4n
    const int gm0 = blockIdx.x * MT;

    stage(0, bbuf, tid);
    stage(1, bbuf + BUFB, tid);

    for (int i = tid; i < 200; i += NT) {
        sbv[i] = b0[i]; sbv[200 + i] = b1[i]; sbv[400 + i] = b2[i]; sbv[600 + i] = b3[i];
        if (i < 100) sbv[800 + i] = bout[i];
    }
    for (int i = tid; i <= TSTEPS; i += NT) tgs[i] = tg[i];
    for (int i = tid; i < MT * DIMV; i += NT) {
        int m = i / DIMV, c = i - m * DIMV;
        S[m * SST + c] = S0[(size_t)(gm0 + m) * DIMV + c];
    }
    for (int i = tid; i < MT * 8; i += NT) {         // zero A kpairs 100..107
        int row = i >> 3, kp = 100 + (i & 7);
        Ahi[row * AST + kp] = 0; Alo[row * AST + kp] = 0;
    }
    __syncthreads();
    const float h = tgs[1] - tgs[0];
    const float sqh = sqrtf(h);

    int gc = 0;
    for (int t = 0; t < TSTEPS; ++t) {
        // build A0 = [t | S | 0pad] as fp16 hi/lo, kpairs 0..55
        {
            int row = tid >> 3, q = tid & 7;
            float tval = tgs[t];
            #pragma unroll
            for (int jj = 0; jj < 7; ++jj) {
                int j = q * 7 + jj, k0 = 2 * j;
                float f0 = (k0 == 0) ? tval : ((k0 <= 100) ? S[row * SST + k0 - 1] : 0.0f);
                float f1 = (k0 + 1 <= 100) ? S[row * SST + k0] : 0.0f;
                uint32_t hi, lo; hsplit2(f0, f1, hi, lo);
                Ahi[row * AST + j] = hi; Alo[row * AST + j] = lo;
            }
        }
        gemm_hidden(7,  4, Ahi, Alo, bbuf, gc, sbv,       wm, wn, g, tq, tid);
        gemm_hidden(13, 7, Ahi, Alo, bbuf, gc, sbv + 200, wm, wn, g, tq, tid);
        gemm_hidden(13, 7, Ahi, Alo, bbuf, gc, sbv + 400, wm, wn, g, tq, tid);
        gemm_hidden(13, 7, Ahi, Alo, bbuf, gc, sbv + 600, wm, wn, g, tq, tid);

        // ---- output layer (13 ksteps, 7 chunks, npad 104, n-tiles 8 interleaved) ----
        float acc[4][4];
        #pragma unroll
        for (int b = 0; b < 4; ++b)
            #pragma unroll
            for (int c = 0; c < 4; ++c) acc[b][c] = 0.0f;

        for (int ch = 0; ch < 7; ++ch) {
            int nk = 13 - 2 * ch; if (nk > 2) nk = 2;
            chunk_sync(gc);
            if (gc + 2 < TOTCH) stage((gc + 2) % NCHSTEP, bbuf + ((gc + 2) % 3) * BUFB, tid);
            const char* bc = bbuf + (gc % 3) * BUFB;

            for (int ki = 0; ki < nk; ++ki) {
                int ks = 2 * ch + ki;
                uint32_t Ah[4], Al[4];
                #pragma unroll
                for (int r = 0; r < 4; ++r) {
                    int row = wm * 16 + g + (r & 1) * 8;
                    int kp  = ks * 8 + tq + (r >> 1) * 4;
                    Ah[r] = Ahi[row * AST + kp];
                    Al[r] = Alo[row * AST + kp];
                }
                const char* bck = bc + ki * KSB;
                #pragma unroll
                for (int nf = 0; nf < 4; ++nf) {
                    int base = nf * 32 + wn * 8;
                    if (base >= 104) break;
                    const char* bp = bck + (base + g) * 48 + tq * 4;
                    uint32_t Bh[2], Bl[2];
                    Bh[0] = *(const uint32_t*)bp;
                    Bh[1] = *(const uint32_t*)(bp + 16);
                    Bl[0] = *(const uint32_t*)(bp + 104 * 48);
                    Bl[1] = *(const uint32_t*)(bp + 104 * 48 + 16);
                    mma16816(acc[nf], Ah, Bh);
                    mma16816(acc[nf], Ah, Bl);
                    mma16816(acc[nf], Al, Bh);
                }
            }
            ++gc;
        }
        __syncthreads();

        // ---- SDE epilogue: u = D + bout; err->out (rmw); S update ----
        #pragma unroll
        for (int nf = 0; nf < 4; ++nf) {
            int base = nf * 32 + wn * 8;
            if (base >= 104) break;
            int n0 = base + tq * 2;
            if (n0 < 100) {
                float bv0 = sbv[800 + n0], bv1 = sbv[800 + n0 + 1];
                #pragma unroll
                for (int hf = 0; hf < 2; ++hf) {
                    int m = wm * 16 + g + 8 * hf;
                    float u0 = acc[nf][2 * hf]     + bv0;
                    float u1 = acc[nf][2 * hf + 1] + bv1;
                    float2 dw = *(const float2*)(dW + (size_t)(gm0 + m) * 10100
                                                    + (size_t)t * DIMV + n0);
                    float s0 = S[m * SST + n0]     + u0 * (h + sqh * dw.x);
                    float s1 = S[m * SST + n0 + 1] + u1 * (h + sqh * dw.y);
                    float2* op = (float2*)(out + (size_t)(gm0 + m) * DIMV + n0);
                    float2 prev = (t == 0) ? make_float2(0.0f, 0.0f) : *op;
                    float o0 = prev.x + u0 * u0 * h;
                    float o1 = prev.y + u1 * u1 * h;
                    if (t == TSTEPS - 1) { o0 += s0 * s0; o1 += s1 * s1; }
                    else { S[m * SST + n0] = s0; S[m * SST + n0 + 1] = s1; }
                    *op = make_float2(o0, o1);
                }
            }
        }
        __syncthreads();   // S stable before next build_A0
    }
    cpwait<0>();
}

extern "C" void kernel_launch(void* const* d_in, const int* in_sizes, int n_in,
                              void* d_out, int out_size) {
    const float* S0   = (const float*)d_in[0];
    const float* tg   = (const float*)d_in[1];
    const float* dW   = (const float*)d_in[2];
    const float* W0   = (const float*)d_in[3];
    const float* b0   = (const float*)d_in[4];
    const float* W1   = (const float*)d_in[5];
    const float* b1   = (const float*)d_in[6];
    const float* W2   = (const float*)d_in[7];
    const float* b2   = (const float*)d_in[8];
    const float* W3   = (const float*)d_in[9];
    const float* b3   = (const float*)d_in[10];
    const float* Wout = (const float*)d_in[11];
    const float* bout = (const float*)d_in[12];
    float* out = (float*)d_out;

    pack_b<<<(7  * 200 * 8 + 255) / 256, 256>>>(W0,   101, 200, 200, 7,  OFF_L0);
    pack_b<<<(13 * 200 * 8 + 255) / 256, 256>>>(W1,   200, 200, 200, 13, OFF_L1);
    pack_b<<<(13 * 200 * 8 + 255) / 256, 256>>>(W2,   200, 200, 200, 13, OFF_L2);
    pack_b<<<(13 * 200 * 8 + 255) / 256, 256>>>(W3,   200, 200, 200, 13, OFF_L3);
    pack_b<<<(13 * 104 * 8 + 255) / 256, 256>>>(Wout, 200, 100, 104, 13, OFF_LO);

    cudaFuncSetAttribute(control_solver_hmma,
                         cudaFuncAttributeMaxDynamicSharedMemorySize, SMEM_BYTES);
    control_solver_hmma<<<4096 / MT, NT, SMEM_BYTES>>>(
        S0, tg, dW, b0, b1, b2, b3, bout, out);
}

// round 11
// speedup vs baseline: 2.8813x; 2.0024x over previous
#include <cuda_runtime.h>
#include <cuda_fp16.h>
#include <math.h>
#include <stdint.h>

#define DIMV   100
#define TSTEPS 100
#define NT     256
#define MT     32          // rows per CTA -> 128 CTAs
#define AST    108         // A row stride in u32 (conflict-free)
#define SST    102         // S row stride in floats

// weight pool: per layer, per k16-step: [npad][16] u32:
//   slot = n*16 + tq*4 + {0:hi(kp=tq),1:hi(kp=tq+4),2:lo(kp=tq),3:lo(kp=tq+4)}
#define OFF_L0 0           // 7  ksteps * 200*16 = 22400
#define OFF_L1 22400       // 13 * 3200 = 41600
#define OFF_L2 64000
#define OFF_L3 105600
#define OFF_LO 147200      // 13 * 104*16 = 21632
__device__ __align__(16) uint32_t g_Bpk[168832];

// ---------- helpers ----------
__device__ __forceinline__ void hsplit2(float f0, float f1, uint32_t& hi, uint32_t& lo) {
    __half h0 = __float2half_rn(f0), h1 = __float2half_rn(f1);
    __half l0 = __float2half_rn(f0 - __half2float(h0));
    __half l1 = __float2half_rn(f1 - __half2float(h1));
    hi = ((uint32_t)__half_as_ushort(h1) << 16) | __half_as_ushort(h0);
    lo = ((uint32_t)__half_as_ushort(l1) << 16) | __half_as_ushort(l0);
}
__device__ __forceinline__ void mma16816(float* c, const uint32_t* a, const uint32_t* b) {
    asm volatile("mma.sync.aligned.m16n8k16.row.col.f32.f16.f16.f32 "
        "{%0,%1,%2,%3}, {%4,%5,%6,%7}, {%8,%9}, {%0,%1,%2,%3};"
        : "+f"(c[0]), "+f"(c[1]), "+f"(c[2]), "+f"(c[3])
        : "r"(a[0]), "r"(a[1]), "r"(a[2]), "r"(a[3]), "r"(b[0]), "r"(b[1]));
}

// ---------- weight pack: fp16 split + transpose + fragment-quad interleave ----------
__global__ void pack_b(const float* __restrict__ W, int Kr, int Nr, int npad,
                       int ksteps, int off) {
    int idx = blockIdx.x * blockDim.x + threadIdx.x;
    if (idx >= ksteps * npad * 8) return;
    int ks = idx / (npad * 8), r = idx - ks * npad * 8, n = r >> 3, kp = r & 7;
    int k0 = ks * 16 + kp * 2, k1 = k0 + 1;
    float v0 = (k0 < Kr && n < Nr) ? W[(size_t)k0 * Nr + n] : 0.0f;
    float v1 = (k1 < Kr && n < Nr) ? W[(size_t)k1 * Nr + n] : 0.0f;
    uint32_t hi, lo; hsplit2(v0, v1, hi, lo);
    int tq = kp & 3, hs = kp >> 2;
    int b = off + ks * npad * 16 + n * 16 + tq * 4;
    g_Bpk[b + hs]     = hi;
    g_Bpk[b + 2 + hs] = lo;
}

// ---------- hidden-layer GEMM + epilogue (warp grid 2m x 4n, 16 rows/warp) ----------
template<int KS>
__device__ __forceinline__ void gemm_hidden(
    uint32_t* Ahi, uint32_t* Alo, const uint32_t* pool, const float* bias,
    int wm, int wn, int g, int tq)
{
    float acc[7][4];
    #pragma unroll
    for (int b = 0; b < 7; ++b)
        #pragma unroll
        for (int c = 0; c < 4; ++c) acc[b][c] = 0.0f;

    const uint32_t* pb = pool + (size_t)(wn * 56 + g) * 16 + tq * 4;
    uint4 B[2][7];
    #pragma unroll
    for (int nf = 0; nf < 7; ++nf)
        if (wn * 56 + nf * 8 < 200) B[0][nf] = *(const uint4*)(pb + nf * 128);

    #pragma unroll
    for (int ks = 0; ks < KS; ++ks) {
        const int cb = ks & 1;
        if (ks + 1 < KS) {
            const uint32_t* p2 = pb + (size_t)(ks + 1) * 3200;
            #pragma unroll
            for (int nf = 0; nf < 7; ++nf)
                if (wn * 56 + nf * 8 < 200) B[cb ^ 1][nf] = *(const uint4*)(p2 + nf * 128);
        }
        uint32_t Ah[4], Al[4];
        #pragma unroll
        for (int r = 0; r < 4; ++r) {
            int row = wm * 16 + g + (r & 1) * 8;
            int kp  = ks * 8 + tq + (r >> 1) * 4;
            Ah[r] = Ahi[row * AST + kp];
            Al[r] = Alo[row * AST + kp];
        }
        #pragma unroll
        for (int nf = 0; nf < 7; ++nf) {
            if (wn * 56 + nf * 8 >= 200) break;
            uint32_t Bh[2] = { B[cb][nf].x, B[cb][nf].y };
            uint32_t Bl[2] = { B[cb][nf].z, B[cb][nf].w };
            mma16816(acc[nf], Ah, Bh);
            mma16816(acc[nf], Ah, Bl);
            mma16816(acc[nf], Al, Bh);
        }
    }
    __syncthreads();   // all reads of A done before overwriting

    #pragma unroll
    for (int nf = 0; nf < 7; ++nf) {
        int base = wn * 56 + nf * 8;
        if (base >= 200) break;
        int n0 = base + tq * 2;
        float bv0 = bias[n0], bv1 = bias[n0 + 1];
        int kp = (base >> 1) + tq;
        int row = wm * 16 + g;
        uint32_t hi, lo;
        hsplit2(fmaxf(acc[nf][0] + bv0, 0.0f), fmaxf(acc[nf][1] + bv1, 0.0f), hi, lo);
        Ahi[row * AST + kp] = hi; Alo[row * AST + kp] = lo;
        hsplit2(fmaxf(acc[nf][2] + bv0, 0.0f), fmaxf(acc[nf][3] + bv1, 0.0f), hi, lo);
        Ahi[(row + 8) * AST + kp] = hi; Alo[(row + 8) * AST + kp] = lo;
    }
    __syncthreads();   // new A visible before next layer reads
}

// ---------- main persistent kernel ----------
#define SMEM_BYTES 46000

__global__ void __launch_bounds__(NT, 1)
control_solver_hmma(
    const float* __restrict__ S0, const float* __restrict__ tg,
    const float* __restrict__ dW,
    const float* __restrict__ b0, const float* __restrict__ b1,
    const float* __restrict__ b2, const float* __restrict__ b3,
    const float* __restrict__ bout, float* __restrict__ out)
{
    extern __shared__ __align__(16) char smc[];
    uint32_t* Ahi = (uint32_t*)smc;                  // 32*108*4 = 13824 B
    uint32_t* Alo = Ahi + MT * AST;                  // 13824 B
    float* S      = (float*)(Alo + MT * AST);        // 32*102*4 = 13056 B
    float* sbv    = S + MT * SST;                    // 900 biases
    float* tgs    = sbv + 900;                       // 101 timegrid

    const int tid = threadIdx.x, warp = tid >> 5, lane = tid & 31;
    const int g = lane >> 2, tq = lane & 3;
    const int wm = warp >> 2, wn = warp & 3;          // 2m x 4n
    const int gm0 = blockIdx.x * MT;

    for (int i = tid; i < 200; i += NT) {
        sbv[i] = b0[i]; sbv[200 + i] = b1[i]; sbv[400 + i] = b2[i]; sbv[600 + i] = b3[i];
        if (i < 100) sbv[800 + i] = bout[i];
    }
    for (int i = tid; i <= TSTEPS; i += NT) tgs[i] = tg[i];
    for (int i = tid; i < MT * DIMV; i += NT) {
        int m = i / DIMV, c = i - m * DIMV;
        S[m * SST + c] = S0[(size_t)(gm0 + m) * DIMV + c];
    }
    for (int i = tid; i < MT * 8; i += NT) {         // zero A kpairs 100..107
        int row = i >> 3, kp = 100 + (i & 7);
        Ahi[row * AST + kp] = 0; Alo[row * AST + kp] = 0;
    }
    __syncthreads();
    const float h = tgs[1] - tgs[0];
    const float sqh = sqrtf(h);

    for (int t = 0; t < TSTEPS; ++t) {
        // build A0 = [t | S | 0pad] as fp16 hi/lo, kpairs 0..55
        {
            int row = tid >> 3, q = tid & 7;
            float tval = tgs[t];
            #pragma unroll
            for (int jj = 0; jj < 7; ++jj) {
                int j = q * 7 + jj, k0 = 2 * j;
                float f0 = (k0 == 0) ? tval : ((k0 <= 100) ? S[row * SST + k0 - 1] : 0.0f);
                float f1 = (k0 + 1 <= 100) ? S[row * SST + k0] : 0.0f;
                uint32_t hi, lo; hsplit2(f0, f1, hi, lo);
                Ahi[row * AST + j] = hi; Alo[row * AST + j] = lo;
            }
        }
        __syncthreads();   // A0 visible to all warps

        gemm_hidden<7> (Ahi, Alo, g_Bpk + OFF_L0, sbv,       wm, wn, g, tq);
        gemm_hidden<13>(Ahi, Alo, g_Bpk + OFF_L1, sbv + 200, wm, wn, g, tq);
        gemm_hidden<13>(Ahi, Alo, g_Bpk + OFF_L2, sbv + 400, wm, wn, g, tq);
        gemm_hidden<13>(Ahi, Alo, g_Bpk + OFF_L3, sbv + 600, wm, wn, g, tq);

        // ---- output layer (13 ksteps, npad 104) ----
        float acc[4][4];
        #pragma unroll
        for (int b = 0; b < 4; ++b)
            #pragma unroll
            for (int c = 0; c < 4; ++c) acc[b][c] = 0.0f;

        {
            const uint32_t* pb = g_Bpk + OFF_LO + (size_t)(wn * 8 + g) * 16 + tq * 4;
            uint4 B[2][4];
            #pragma unroll
            for (int nf = 0; nf < 4; ++nf)
                if (nf * 32 + wn * 8 < 104) B[0][nf] = *(const uint4*)(pb + nf * 512);

            #pragma unroll
            for (int ks = 0; ks < 13; ++ks) {
                const int cb = ks & 1;
                if (ks + 1 < 13) {
                    const uint32_t* p2 = pb + (size_t)(ks + 1) * 1664;
                    #pragma unroll
                    for (int nf = 0; nf < 4; ++nf)
                        if (nf * 32 + wn * 8 < 104) B[cb ^ 1][nf] = *(const uint4*)(p2 + nf * 512);
                }
                uint32_t Ah[4], Al[4];
                #pragma unroll
                for (int r = 0; r < 4; ++r) {
                    int row = wm * 16 + g + (r & 1) * 8;
                    int kp  = ks * 8 + tq + (r >> 1) * 4;
                    Ah[r] = Ahi[row * AST + kp];
                    Al[r] = Alo[row * AST + kp];
                }
                #pragma unroll
                for (int nf = 0; nf < 4; ++nf) {
                    if (nf * 32 + wn * 8 >= 104) break;
                    uint32_t Bh[2] = { B[cb][nf].x, B[cb][nf].y };
                    uint32_t Bl[2] = { B[cb][nf].z, B[cb][nf].w };
                    mma16816(acc[nf], Ah, Bh);
                    mma16816(acc[nf], Ah, Bl);
                    mma16816(acc[nf], Al, Bh);
                }
            }
        }
        __syncthreads();

        // ---- SDE epilogue: u = D + bout; err->out (rmw); S update ----
        #pragma unroll
        for (int nf = 0; nf < 4; ++nf) {
            int base = nf * 32 + wn * 8;
            if (base >= 104) break;
            int n0 = base + tq * 2;
            if (n0 < 100) {
                float bv0 = sbv[800 + n0], bv1 = sbv[800 + n0 + 1];
                #pragma unroll
                for (int hf = 0; hf < 2; ++hf) {
                    int m = wm * 16 + g + 8 * hf;
                    float u0 = acc[nf][2 * hf]     + bv0;
                    float u1 = acc[nf][2 * hf + 1] + bv1;
                    float2 dw = *(const float2*)(dW + (size_t)(gm0 + m) * 10100
                                                    + (size_t)t * DIMV + n0);
                    float s0 = S[m * SST + n0]     + u0 * (h + sqh * dw.x);
                    float s1 = S[m * SST + n0 + 1] + u1 * (h + sqh * dw.y);
                    float2* op = (float2*)(out + (size_t)(gm0 + m) * DIMV + n0);
                    float2 prev = (t == 0) ? make_float2(0.0f, 0.0f) : *op;
                    float o0 = prev.x + u0 * u0 * h;
                    float o1 = prev.y + u1 * u1 * h;
                    if (t == TSTEPS - 1) { o0 += s0 * s0; o1 += s1 * s1; }
                    else { S[m * SST + n0] = s0; S[m * SST + n0 + 1] = s1; }
                    *op = make_float2(o0, o1);
                }
            }
        }
        __syncthreads();   // S stable before next build_A0
    }
}

extern "C" void kernel_launch(void* const* d_in, const int* in_sizes, int n_in,
                              void* d_out, int out_size) {
    const float* S0   = (const float*)d_in[0];
    const float* tg   = (const float*)d_in[1];
    const float* dW   = (const float*)d_in[2];
    const float* W0   = (const float*)d_in[3];
    const float* b0   = (const float*)d_in[4];
    const float* W1   = (const float*)d_in[5];
    const float* b1   = (const float*)d_in[6];
    const float* W2   = (const float*)d_in[7];
    const float* b2   = (const float*)d_in[8];
    const float* W3   = (const float*)d_in[9];
    const float* b3   = (const float*)d_in[10];
    const float* Wout = (const float*)d_in[11];
    const float* bout = (const float*)d_in[12];
    float* out = (float*)d_out;

    pack_b<<<(7  * 200 * 8 + 255) / 256, 256>>>(W0,   101, 200, 200, 7,  OFF_L0);
    pack_b<<<(13 * 200 * 8 + 255) / 256, 256>>>(W1,   200, 200, 200, 13, OFF_L1);
    pack_b<<<(13 * 200 * 8 + 255) / 256, 256>>>(W2,   200, 200, 200, 13, OFF_L2);
    pack_b<<<(13 * 200 * 8 + 255) / 256, 256>>>(W3,   200, 200, 200, 13, OFF_L3);
    pack_b<<<(13 * 104 * 8 + 255) / 256, 256>>>(Wout, 200, 100, 104, 13, OFF_LO);

    cudaFuncSetAttribute(control_solver_hmma,
                         cudaFuncAttributeMaxDynamicSharedMemorySize, SMEM_BYTES);
    control_solver_hmma<<<4096 / MT, NT, SMEM_BYTES>>>(
        S0, tg, dW, b0, b1, b2, b3, bout, out);
}

// round 12
// speedup vs baseline: 3.0971x; 1.0749x over previous
#include <cuda_runtime.h>
#include <cuda_fp16.h>
#include <math.h>
#include <stdint.h>

#define DIMV   100
#define TSTEPS 100
#define NT     256
#define MT     32          // rows per CTA -> 128 CTAs
#define AST    108         // A row stride in u32 (conflict-free)
#define SST    102         // S row stride in floats

// weight pool: per layer, per k16-step: [npad][16] u32:
//   slot = n*16 + tq*4 + {0:hi(kp=tq),1:hi(kp=tq+4),2:lo(kp=tq),3:lo(kp=tq+4)}
#define OFF_L0 0           // 7  ksteps * 200*16 = 22400
#define OFF_L1 22400       // 13 * 3200 = 41600
#define OFF_L2 64000
#define OFF_L3 105600
#define OFF_LO 147200      // 13 * 104*16 = 21632
__device__ __align__(16) uint32_t g_Bpk[168832];

// ---------- helpers ----------
__device__ __forceinline__ void hsplit2(float f0, float f1, uint32_t& hi, uint32_t& lo) {
    __half h0 = __float2half_rn(f0), h1 = __float2half_rn(f1);
    __half l0 = __float2half_rn(f0 - __half2float(h0));
    __half l1 = __float2half_rn(f1 - __half2float(h1));
    hi = ((uint32_t)__half_as_ushort(h1) << 16) | __half_as_ushort(h0);
    lo = ((uint32_t)__half_as_ushort(l1) << 16) | __half_as_ushort(l0);
}
__device__ __forceinline__ void mma16816(float* c, const uint32_t* a, const uint32_t* b) {
    asm volatile("mma.sync.aligned.m16n8k16.row.col.f32.f16.f16.f32 "
        "{%0,%1,%2,%3}, {%4,%5,%6,%7}, {%8,%9}, {%0,%1,%2,%3};"
        : "+f"(c[0]), "+f"(c[1]), "+f"(c[2]), "+f"(c[3])
        : "r"(a[0]), "r"(a[1]), "r"(a[2]), "r"(a[3]), "r"(b[0]), "r"(b[1]));
}

// ---------- weight pack: fp16 split + transpose + fragment-quad interleave ----------
__global__ void pack_b(const float* __restrict__ W, int Kr, int Nr, int npad,
                       int ksteps, int off) {
    int idx = blockIdx.x * blockDim.x + threadIdx.x;
    if (idx >= ksteps * npad * 8) return;
    int ks = idx / (npad * 8), r = idx - ks * npad * 8, n = r >> 3, kp = r & 3 + 0;
    kp = r & 7;
    int k0 = ks * 16 + kp * 2, k1 = k0 + 1;
    float v0 = (k0 < Kr && n < Nr) ? W[(size_t)k0 * Nr + n] : 0.0f;
    float v1 = (k1 < Kr && n < Nr) ? W[(size_t)k1 * Nr + n] : 0.0f;
    uint32_t hi, lo; hsplit2(v0, v1, hi, lo);
    int tq = kp & 3, hs = kp >> 2;
    int b = off + ks * npad * 16 + n * 16 + tq * 4;
    g_Bpk[b + hs]     = hi;
    g_Bpk[b + 2 + hs] = lo;
}

// ---------- hidden-layer GEMM + epilogue (1m x 8n grid, mf=2, 32 rows/warp) ----------
template<int KS>
__device__ __forceinline__ void gemm_hidden(
    uint32_t* Ahi, uint32_t* Alo, const uint32_t* pool, const float* bias,
    int wn, int g, int tq)
{
    float acc[2][4][4];
    #pragma unroll
    for (int m = 0; m < 2; ++m)
        #pragma unroll
        for (int b = 0; b < 4; ++b)
            #pragma unroll
            for (int c = 0; c < 4; ++c) acc[m][b][c] = 0.0f;

    const uint32_t* pb = pool + (size_t)g * 16 + tq * 4;
    uint4 B[2][4];
    #pragma unroll
    for (int j = 0; j < 4; ++j) {
        int nt = wn + 8 * j;
        if (nt < 25) B[0][j] = *(const uint4*)(pb + nt * 128);
    }

    #pragma unroll
    for (int ks = 0; ks < KS; ++ks) {
        const int cb = ks & 1;
        if (ks + 1 < KS) {
            const uint32_t* p2 = pb + (size_t)(ks + 1) * 3200;
            #pragma unroll
            for (int j = 0; j < 4; ++j) {
                int nt = wn + 8 * j;
                if (nt < 25) B[cb ^ 1][j] = *(const uint4*)(p2 + nt * 128);
            }
        }
        uint32_t Ah[2][4], Al[2][4];
        #pragma unroll
        for (int mf = 0; mf < 2; ++mf)
            #pragma unroll
            for (int r = 0; r < 4; ++r) {
                int row = mf * 16 + g + (r & 1) * 8;
                int kp  = ks * 8 + tq + (r >> 1) * 4;
                Ah[mf][r] = Ahi[row * AST + kp];
                Al[mf][r] = Alo[row * AST + kp];
            }
        #pragma unroll
        for (int j = 0; j < 4; ++j) {
            int nt = wn + 8 * j;
            if (nt < 25) {
                uint32_t Bh[2] = { B[cb][j].x, B[cb][j].y };
                uint32_t Bl[2] = { B[cb][j].z, B[cb][j].w };
                #pragma unroll
                for (int mf = 0; mf < 2; ++mf) {
                    mma16816(acc[mf][j], Ah[mf], Bh);
                    mma16816(acc[mf][j], Ah[mf], Bl);
                    mma16816(acc[mf][j], Al[mf], Bh);
                }
            }
        }
    }
    __syncthreads();   // all reads of A done before overwriting

    #pragma unroll
    for (int j = 0; j < 4; ++j) {
        int nt = wn + 8 * j;
        if (nt < 25) {
            int n0 = nt * 8 + tq * 2;
            float bv0 = bias[n0], bv1 = bias[n0 + 1];
            int kp = nt * 4 + tq;
            #pragma unroll
            for (int mf = 0; mf < 2; ++mf) {
                int row = mf * 16 + g;
                uint32_t hi, lo;
                hsplit2(fmaxf(acc[mf][j][0] + bv0, 0.0f),
                        fmaxf(acc[mf][j][1] + bv1, 0.0f), hi, lo);
                Ahi[row * AST + kp] = hi; Alo[row * AST + kp] = lo;
                hsplit2(fmaxf(acc[mf][j][2] + bv0, 0.0f),
                        fmaxf(acc[mf][j][3] + bv1, 0.0f), hi, lo);
                Ahi[(row + 8) * AST + kp] = hi; Alo[(row + 8) * AST + kp] = lo;
            }
        }
    }
    __syncthreads();   // new A visible before next layer reads
}

// ---------- main persistent kernel ----------
#define SMEM_BYTES 46000

__global__ void __launch_bounds__(NT, 1)
control_solver_hmma(
    const float* __restrict__ S0, const float* __restrict__ tg,
    const float* __restrict__ dW,
    const float* __restrict__ b0, const float* __restrict__ b1,
    const float* __restrict__ b2, const float* __restrict__ b3,
    const float* __restrict__ bout, float* __restrict__ out)
{
    extern __shared__ __align__(16) char smc[];
    uint32_t* Ahi = (uint32_t*)smc;                  // 32*108*4 = 13824 B
    uint32_t* Alo = Ahi + MT * AST;                  // 13824 B
    float* S      = (float*)(Alo + MT * AST);        // 32*102*4 = 13056 B
    float* sbv    = S + MT * SST;                    // 900 biases
    float* tgs    = sbv + 900;                       // 101 timegrid

    const int tid = threadIdx.x, warp = tid >> 5, lane = tid & 31;
    const int g = lane >> 2, tq = lane & 3;
    const int wn = warp;                              // 1m x 8n
    const int gm0 = blockIdx.x * MT;

    for (int i = tid; i < 200; i += NT) {
        sbv[i] = b0[i]; sbv[200 + i] = b1[i]; sbv[400 + i] = b2[i]; sbv[600 + i] = b3[i];
        if (i < 100) sbv[800 + i] = bout[i];
    }
    for (int i = tid; i <= TSTEPS; i += NT) tgs[i] = tg[i];
    for (int i = tid; i < MT * DIMV; i += NT) {
        int m = i / DIMV, c = i - m * DIMV;
        S[m * SST + c] = S0[(size_t)(gm0 + m) * DIMV + c];
    }
    for (int i = tid; i < MT * 8; i += NT) {         // zero A kpairs 100..107
        int row = i >> 3, kp = 100 + (i & 7);
        Ahi[row * AST + kp] = 0; Alo[row * AST + kp] = 0;
    }
    __syncthreads();
    const float h = tgs[1] - tgs[0];
    const float sqh = sqrtf(h);

    for (int t = 0; t < TSTEPS; ++t) {
        // build A0 = [t | S | 0pad] as fp16 hi/lo, kpairs 0..55
        {
            int row = tid >> 3, q = tid & 7;
            float tval = tgs[t];
            #pragma unroll
            for (int jj = 0; jj < 7; ++jj) {
                int j = q * 7 + jj, k0 = 2 * j;
                float f0 = (k0 == 0) ? tval : ((k0 <= 100) ? S[row * SST + k0 - 1] : 0.0f);
                float f1 = (k0 + 1 <= 100) ? S[row * SST + k0] : 0.0f;
                uint32_t hi, lo; hsplit2(f0, f1, hi, lo);
                Ahi[row * AST + j] = hi; Alo[row * AST + j] = lo;
            }
        }
        __syncthreads();   // A0 visible to all warps

        gemm_hidden<7> (Ahi, Alo, g_Bpk + OFF_L0, sbv,       wn, g, tq);
        gemm_hidden<13>(Ahi, Alo, g_Bpk + OFF_L1, sbv + 200, wn, g, tq);
        gemm_hidden<13>(Ahi, Alo, g_Bpk + OFF_L2, sbv + 400, wn, g, tq);
        gemm_hidden<13>(Ahi, Alo, g_Bpk + OFF_L3, sbv + 600, wn, g, tq);

        // ---- output layer (13 ksteps, npad 104, n-tiles wn + 8j, j<2) ----
        float acc[2][2][4];
        #pragma unroll
        for (int m = 0; m < 2; ++m)
            #pragma unroll
            for (int b = 0; b < 2; ++b)
                #pragma unroll
                for (int c = 0; c < 4; ++c) acc[m][b][c] = 0.0f;

        {
            const uint32_t* pb = g_Bpk + OFF_LO + (size_t)g * 16 + tq * 4;
            uint4 B[2][2];
            #pragma unroll
            for (int j = 0; j < 2; ++j) {
                int nt = wn + 8 * j;
                if (nt < 13) B[0][j] = *(const uint4*)(pb + nt * 128);
            }
            #pragma unroll
            for (int ks = 0; ks < 13; ++ks) {
                const int cb = ks & 1;
                if (ks + 1 < 13) {
                    const uint32_t* p2 = pb + (size_t)(ks + 1) * 1664;
                    #pragma unroll
                    for (int j = 0; j < 2; ++j) {
                        int nt = wn + 8 * j;
                        if (nt < 13) B[cb ^ 1][j] = *(const uint4*)(p2 + nt * 128);
                    }
                }
                uint32_t Ah[2][4], Al[2][4];
                #pragma unroll
                for (int mf = 0; mf < 2; ++mf)
                    #pragma unroll
                    for (int r = 0; r < 4; ++r) {
                        int row = mf * 16 + g + (r & 1) * 8;
                        int kp  = ks * 8 + tq + (r >> 1) * 4;
                        Ah[mf][r] = Ahi[row * AST + kp];
                        Al[mf][r] = Alo[row * AST + kp];
                    }
                #pragma unroll
                for (int j = 0; j < 2; ++j) {
                    int nt = wn + 8 * j;
                    if (nt < 13) {
                        uint32_t Bh[2] = { B[cb][j].x, B[cb][j].y };
                        uint32_t Bl[2] = { B[cb][j].z, B[cb][j].w };
                        #pragma unroll
                        for (int mf = 0; mf < 2; ++mf) {
                            mma16816(acc[mf][j], Ah[mf], Bh);
                            mma16816(acc[mf][j], Ah[mf], Bl);
                            mma16816(acc[mf][j], Al[mf], Bh);
                        }
                    }
                }
            }
        }
        __syncthreads();

        // ---- SDE epilogue: u = D + bout; err->out (rmw); S update ----
        #pragma unroll
        for (int j = 0; j < 2; ++j) {
            int nt = wn + 8 * j;
            if (nt < 13) {
                int n0 = nt * 8 + tq * 2;
                if (n0 < 100) {
                    float bv0 = sbv[800 + n0], bv1 = sbv[800 + n0 + 1];
                    #pragma unroll
                    for (int mf = 0; mf < 2; ++mf)
                        #pragma unroll
                        for (int hf = 0; hf < 2; ++hf) {
                            int m = mf * 16 + g + 8 * hf;
                            float u0 = acc[mf][j][2 * hf]     + bv0;
                            float u1 = acc[mf][j][2 * hf + 1] + bv1;
                            float2 dw = *(const float2*)(dW + (size_t)(gm0 + m) * 10100
                                                            + (size_t)t * DIMV + n0);
                            float s0 = S[m * SST + n0]     + u0 * (h + sqh * dw.x);
                            float s1 = S[m * SST + n0 + 1] + u1 * (h + sqh * dw.y);
                            float2* op = (float2*)(out + (size_t)(gm0 + m) * DIMV + n0);
                            float2 prev = (t == 0) ? make_float2(0.0f, 0.0f) : *op;
                            float o0 = prev.x + u0 * u0 * h;
                            float o1 = prev.y + u1 * u1 * h;
                            if (t == TSTEPS - 1) { o0 += s0 * s0; o1 += s1 * s1; }
                            else { S[m * SST + n0] = s0; S[m * SST + n0 + 1] = s1; }
                            *op = make_float2(o0, o1);
                        }
                }
            }
        }
        __syncthreads();   // S stable before next build_A0
    }
}

extern "C" void kernel_launch(void* const* d_in, const int* in_sizes, int n_in,
                              void* d_out, int out_size) {
    const float* S0   = (const float*)d_in[0];
    const float* tg   = (const float*)d_in[1];
    const float* dW   = (const float*)d_in[2];
    const float* W0   = (const float*)d_in[3];
    const float* b0   = (const float*)d_in[4];
    const float* W1   = (const float*)d_in[5];
    const float* b1   = (const float*)d_in[6];
    const float* W2   = (const float*)d_in[7];
    const float* b2   = (const float*)d_in[8];
    const float* W3   = (const float*)d_in[9];
    const float* b3   = (const float*)d_in[10];
    const float* Wout = (const float*)d_in[11];
    const float* bout = (const float*)d_in[12];
    float* out = (float*)d_out;

    pack_b<<<(7  * 200 * 8 + 255) / 256, 256>>>(W0,   101, 200, 200, 7,  OFF_L0);
    pack_b<<<(13 * 200 * 8 + 255) / 256, 256>>>(W1,   200, 200, 200, 13, OFF_L1);
    pack_b<<<(13 * 200 * 8 + 255) / 256, 256>>>(W2,   200, 200, 200, 13, OFF_L2);
    pack_b<<<(13 * 200 * 8 + 255) / 256, 256>>>(W3,   200, 200, 200, 13, OFF_L3);
    pack_b<<<(13 * 104 * 8 + 255) / 256, 256>>>(Wout, 200, 100, 104, 13, OFF_LO);

    cudaFuncSetAttribute(control_solver_hmma,
                         cudaFuncAttributeMaxDynamicSharedMemorySize, SMEM_BYTES);
    control_solver_hmma<<<4096 / MT, NT, SMEM_BYTES>>>(
        S0, tg, dW, b0, b1, b2, b3, bout, out);
}